// round 10
// baseline (speedup 1.0000x reference)
#include <cuda_runtime.h>
#include <cuda_bf16.h>
#include <cuda_fp8.h>
#include <math.h>
#include <stdint.h>

// ---------------- problem constants ----------------------------------------
#define DDIM   256
#define KTOP   8
#define CDEP   4            // per-thread per-row candidate depth (gemm)
#define CPS    32           // candidates per (query, split) = 8 slots x CDEP
#define CTOP   24           // merged candidates re-ranked exactly in fp32
#define QT     128          // queries per CTA (M)
#define NT     128          // memory rows per tile (N)
#define NSPLIT 18           // 16 x 18 = 288 CTAs; 2 CTA/SM -> one wave of 296
#define NPAD_MAX 100096
#define BQ_MAX   2048

// ---------------- device scratch (static, no dynamic alloc) ----------------
__device__ uint8_t g_qe[(size_t)BQ_MAX   * DDIM];   // normalized queries, e4m3 x16
__device__ uint8_t g_me[(size_t)NPAD_MAX * DDIM];   // normalized memory,  e4m3 x16
__device__ float   g_minv[NPAD_MAX];                // 1/max(||m||, eps)
__device__ float g_cand_val[(size_t)BQ_MAX * NSPLIT * CPS];
__device__ int   g_cand_idx[(size_t)BQ_MAX * NSPLIT * CPS];

// ---------------- PTX helpers (plain-target instructions only) -------------
__device__ __forceinline__ uint32_t smem_to_u32(const void* p) {
    uint32_t a;
    asm("{ .reg .u64 t; cvta.to.shared.u64 t, %1; cvt.u32.u64 %0, t; }"
        : "=r"(a) : "l"(p));
    return a;
}

#define CP_ASYNC16(s, g) \
    asm volatile("cp.async.cg.shared.global [%0], [%1], 16;" :: "r"(s), "l"(g))
#define CP_COMMIT() asm volatile("cp.async.commit_group;" ::: "memory")
#define CP_WAIT(n)  asm volatile("cp.async.wait_group %0;" :: "n"(n) : "memory")

__device__ __forceinline__ void ldsm4(uint32_t* r, uint32_t a) {
    asm volatile("ldmatrix.sync.aligned.m8n8.x4.shared.b16 {%0,%1,%2,%3}, [%4];"
        : "=r"(r[0]), "=r"(r[1]), "=r"(r[2]), "=r"(r[3]) : "r"(a));
}

// fp8 e4m3 MMA: D(16x8,f32) += A(16x32) * B(32x8)
__device__ __forceinline__ void mma16832(float* d, const uint32_t* a,
                                         uint32_t b0, uint32_t b1) {
    asm volatile(
        "mma.sync.aligned.m16n8k32.row.col.f32.e4m3.e4m3.f32 "
        "{%0,%1,%2,%3}, {%4,%5,%6,%7}, {%8,%9}, {%0,%1,%2,%3};"
        : "+f"(d[0]), "+f"(d[1]), "+f"(d[2]), "+f"(d[3])
        : "r"(a[0]), "r"(a[1]), "r"(a[2]), "r"(a[3]), "r"(b0), "r"(b1));
}

// ---------------- fused normalize: mem + query rows, one launch ------------
__device__ __forceinline__ uint32_t pack_e4m3x4(float x, float y, float z, float w) {
    __nv_fp8x4_e4m3 p(make_float4(x, y, z, w));
    return *reinterpret_cast<uint32_t*>(&p);
}

__global__ void norm_kernel(const float* __restrict__ q,
                            const float* __restrict__ m,
                            int B, int Nvalid, int Ntot) {
    const int warp = (blockIdx.x * blockDim.x + threadIdx.x) >> 5;
    const int lane = threadIdx.x & 31;
    const bool is_mem = warp < Ntot;
    if (!is_mem && warp - Ntot >= B) return;

    const int row = is_mem ? warp : warp - Ntot;
    if (is_mem && row >= Nvalid) {   // zero pad rows
        uint32_t* dst = (uint32_t*)(g_me + (size_t)row * DDIM);
        dst[lane] = 0u; dst[lane + 32] = 0u;
        if (lane == 0) g_minv[row] = 0.f;
        return;
    }
    const float* in = is_mem ? m : q;
    uint32_t* dst = (uint32_t*)((is_mem ? g_me : g_qe) + (size_t)row * DDIM);

    const float4* src = (const float4*)(in + (size_t)row * DDIM);
    float4 a = src[lane];
    float4 b = src[lane + 32];
    float ss = a.x*a.x + a.y*a.y + a.z*a.z + a.w*a.w
             + b.x*b.x + b.y*b.y + b.z*b.z + b.w*b.w;
    #pragma unroll
    for (int o = 16; o > 0; o >>= 1) ss += __shfl_xor_sync(0xffffffffu, ss, o);
    float invn = 1.0f / fmaxf(sqrtf(ss), 1e-12f);
    float inv  = 16.0f * invn;                    // x16 centers e4m3 range
    dst[lane]      = pack_e4m3x4(a.x*inv, a.y*inv, a.z*inv, a.w*inv);
    dst[lane + 32] = pack_e4m3x4(b.x*inv, b.y*inv, b.z*inv, b.w*inv);
    if (is_mem && lane == 0) g_minv[row] = invn;
}

// ---------------- top-L insertion (ascending, v[0]=min) --------------------
template <int L>
__device__ __forceinline__ void insL(float s, int n, float* v, int* id) {
    #pragma unroll
    for (int i = 0; i < L; ++i) {
        if (s > v[i]) {
            bool up = (i < L - 1) && (s > v[i + 1]);
            float nv = up ? v[i + 1] : s;
            int   ni = up ? id[i + 1] : n;
            v[i] = nv; id[i] = ni;
        }
    }
}

template <int L>
__device__ __forceinline__ void insL_tie(float s, int n, float* v, int* id) {
    #pragma unroll
    for (int i = 0; i < L; ++i) {
        bool better = (s > v[i]) || (s == v[i] && n < id[i]);
        if (better) {
            bool up = (i < L - 1) && ((s > v[i + 1]) || (s == v[i + 1] && n < id[i + 1]));
            float nv = up ? v[i + 1] : s;
            int   ni = up ? id[i + 1] : n;
            v[i] = nv; id[i] = ni;
        }
    }
}

// ---------------- fused fp8 QMMA GEMM + fragment-direct top-4 --------------
// smem: A resident 32KB + B double buffer 2x32KB  -> 2 CTAs/SM
#define SA    0
#define SB0   32768
#define SB1   65536
#define SMEM_BYTES 98304

// load one 128-row x 256-byte fp8 tile with xor-swizzle (16B granules)
__device__ __forceinline__ void load_tile8(uint32_t sbuf, const uint8_t* g, int tid) {
    #pragma unroll
    for (int j = 0; j < 8; ++j) {
        int c_lin = j * 256 + tid;          // 2048 16B chunks
        int row = c_lin >> 4;
        int c   = c_lin & 15;
        uint32_t sw = (uint32_t)(((c ^ row) & 7) | (c & 8));
        CP_ASYNC16(sbuf + (uint32_t)(row * 256) + (sw << 4),
                   g + (size_t)row * 256 + c * 16);
    }
}

__global__ __launch_bounds__(256, 2)
void gemm_topk_kernel(int ntiles) {
    extern __shared__ __align__(16) char smem[];
    const uint32_t sb = smem_to_u32(smem);
    const int tid  = threadIdx.x, lane = tid & 31, wid = tid >> 5;
    const int wm   = wid >> 1, wn = wid & 1;            // 4 x 2 warp grid
    const int m0   = blockIdx.x * QT, split = blockIdx.y;
    const int t0   = (split * ntiles) / NSPLIT;
    const int t1   = ((split + 1) * ntiles) / NSPLIT;

    const int rA = wm * 32 + (lane & 15);
    const int rB = wn * 64 + (lane & 15);
    const int ch = lane >> 4;
    const int xA = rA & 7, xB = rB & 7;

    // per-thread candidates: 4 owned query-rows x depth-4 (ascending)
    float cv[4][CDEP]; int ci[4][CDEP];
    #pragma unroll
    for (int r = 0; r < 4; ++r)
        #pragma unroll
        for (int i = 0; i < CDEP; ++i) { cv[r][i] = -3e38f; ci[r][i] = 0x7fffffff; }

    load_tile8(sb + SA, g_qe + (size_t)m0 * DDIM, tid);
    load_tile8(sb + SB0, g_me + (size_t)t0 * NT * DDIM, tid);
    CP_COMMIT();

    const int colbase = wn * 64 + ((lane & 3) << 1);

    for (int t = t0; t < t1; ++t) {
        const int p = (t - t0) & 1;
        const uint32_t bufB = sb + (p ? SB1 : SB0);

        CP_WAIT(0);
        __syncthreads();
        if (t + 1 < t1) {   // prefetch next B tile into the other buffer
            load_tile8(sb + (p ? SB0 : SB1), g_me + (size_t)(t + 1) * NT * DDIM, tid);
            CP_COMMIT();
        }

        float acc[2][8][4];
        #pragma unroll
        for (int mi = 0; mi < 2; ++mi)
            #pragma unroll
            for (int nj = 0; nj < 8; ++nj)
                #pragma unroll
                for (int e = 0; e < 4; ++e) acc[mi][nj][e] = 0.f;

        const uint32_t bufA = sb + SA;
        #pragma unroll
        for (int ks = 0; ks < 8; ++ks) {
            const int c = ks * 2 + ch;
            const uint32_t swA = (uint32_t)((((c ^ xA) & 7) | (c & 8)) << 4);
            const uint32_t swB = (uint32_t)((((c ^ xB) & 7) | (c & 8)) << 4);
            uint32_t a0[4], a1[4], bfr[4][4];
            ldsm4(a0, bufA + (uint32_t)(rA * 256) + swA);
            ldsm4(a1, bufA + (uint32_t)((rA + 16) * 256) + swA);
            #pragma unroll
            for (int g = 0; g < 4; ++g)
                ldsm4(bfr[g], bufB + (uint32_t)((rB + g * 16) * 256) + swB);
            #pragma unroll
            for (int g = 0; g < 4; ++g) {
                mma16832(acc[0][2*g],     a0, bfr[g][0], bfr[g][2]);
                mma16832(acc[0][2*g + 1], a0, bfr[g][1], bfr[g][3]);
                mma16832(acc[1][2*g],     a1, bfr[g][0], bfr[g][2]);
                mma16832(acc[1][2*g + 1], a1, bfr[g][1], bfr[g][3]);
            }
        }

        // ---- fragment-direct scan with pair-max prefilter -----------------
        const int nb = t * NT + colbase;
        #pragma unroll
        for (int mi = 0; mi < 2; ++mi)
            #pragma unroll
            for (int nj = 0; nj < 8; ++nj) {
                const int n0 = nb + nj * 8;
                float* a = acc[mi][nj];
                if (fmaxf(a[0], a[1]) > cv[2*mi][0]) {
                    insL<CDEP>(a[0], n0,     cv[2*mi], ci[2*mi]);
                    insL<CDEP>(a[1], n0 + 1, cv[2*mi], ci[2*mi]);
                }
                if (fmaxf(a[2], a[3]) > cv[2*mi + 1][0]) {
                    insL<CDEP>(a[2], n0,     cv[2*mi + 1], ci[2*mi + 1]);
                    insL<CDEP>(a[3], n0 + 1, cv[2*mi + 1], ci[2*mi + 1]);
                }
            }
    }

    // ---- write candidates: slot = wn*4 + (lane&3), CDEP entries each ------
    {
        const int er   = wm * 32 + (lane >> 2);
        const int slot = wn * 4 + (lane & 3);
        #pragma unroll
        for (int r = 0; r < 4; ++r) {
            const int qrow = m0 + er + (r >> 1) * 16 + (r & 1) * 8;
            const size_t base = ((size_t)qrow * NSPLIT + split) * CPS + slot * CDEP;
            #pragma unroll
            for (int i = 0; i < CDEP; ++i) {
                g_cand_val[base + i] = cv[r][i];
                g_cand_idx[base + i] = ci[r][i];
            }
        }
    }
}

// ---------------- rerank: phase-split selection + pipelined exact scoring --
#define CANDN (NSPLIT * CPS)   // 576
#define CSLOT (CANDN / 32)     // 18
#define LDEP  8                // per-lane sorted depth (union 256 >= any top-24)

__global__ void rerank_kernel(const float* __restrict__ q,
                              const float* __restrict__ mem,
                              float* __restrict__ out, int B, int N) {
    const int lane = threadIdx.x & 31;
    const int w    = threadIdx.x >> 5;
    const int qi   = blockIdx.x * 8 + w;
    if (qi >= B) return;

    __shared__ int s_idx[8][CTOP];

    // ---- phase A: per-lane sorted top-8, then CTOP pop-max extractions ----
    {
        float hv[LDEP]; int hi[LDEP];
        #pragma unroll
        for (int i = 0; i < LDEP; ++i) { hv[i] = -3e38f; hi[i] = 0x7fffffff; }
        const size_t cb = (size_t)qi * CANDN;
        #pragma unroll
        for (int j = 0; j < CSLOT; ++j) {
            int c = lane + j * 32;
            float s = g_cand_val[cb + c];
            int   n = g_cand_idx[cb + c];
            bool better0 = (s > hv[0]) || (s == hv[0] && n < hi[0]);
            if (better0) insL_tie<LDEP>(s, n, hv, hi);
        }
        #pragma unroll 1
        for (int r = 0; r < CTOP; ++r) {
            float mv = hv[LDEP - 1]; int mi = hi[LDEP - 1];
            float bv = mv; int bi = mi;
            #pragma unroll
            for (int o = 16; o > 0; o >>= 1) {
                float ov = __shfl_xor_sync(0xffffffffu, bv, o);
                int   oi = __shfl_xor_sync(0xffffffffu, bi, o);
                if (ov > bv || (ov == bv && oi < bi)) { bv = ov; bi = oi; }
            }
            if (mv == bv && mi == bi) {   // winner lane pops its max
                #pragma unroll
                for (int i = LDEP - 1; i > 0; --i) { hv[i] = hv[i - 1]; hi[i] = hi[i - 1]; }
                hv[0] = -3e38f; hi[0] = 0x7fffffff;
            }
            if (lane == 0) s_idx[w][r] = bi;
        }
        __syncwarp();
    }

    // ---- normalized query in registers -----------------------------------
    const float4* q4 = (const float4*)(q + (size_t)qi * DDIM);
    float4 qa = q4[lane], qb = q4[lane + 32];
    float qs = qa.x*qa.x + qa.y*qa.y + qa.z*qa.z + qa.w*qa.w
             + qb.x*qb.x + qb.y*qb.y + qb.z*qb.z + qb.w*qb.w;
    #pragma unroll
    for (int o = 16; o > 0; o >>= 1) qs += __shfl_xor_sync(0xffffffffu, qs, o);
    float qn = fmaxf(sqrtf(qs), 1e-12f);
    qa.x /= qn; qa.y /= qn; qa.z /= qn; qa.w /= qn;
    qb.x /= qn; qb.y /= qn; qb.z /= qn; qb.w /= qn;

    // ---- phase B: pipelined exact fp32 scoring of the CTOP candidates -----
    float sv[KTOP]; int si[KTOP];
    #pragma unroll
    for (int i = 0; i < KTOP; ++i) { sv[i] = -3e38f; si[i] = 0x7fffffff; }

    int   n_cur  = s_idx[w][0];
    bool  ok_cur = (unsigned)n_cur < (unsigned)N;
    float4 ma, mb; float iv;
    {
        const float4* m4 = (const float4*)(mem + (size_t)(ok_cur ? n_cur : 0) * DDIM);
        ma = ok_cur ? m4[lane] : make_float4(0,0,0,0);
        mb = ok_cur ? m4[lane + 32] : make_float4(0,0,0,0);
        iv = ok_cur ? g_minv[n_cur] : 0.f;
    }

    #pragma unroll 1
    for (int c = 0; c < CTOP; ++c) {
        float4 cma = ma, cmb = mb; float civ = iv;
        const int  n  = n_cur;
        const bool ok = ok_cur;
        if (c + 1 < CTOP) {          // issue next loads before the reduction
            n_cur  = s_idx[w][c + 1];
            ok_cur = (unsigned)n_cur < (unsigned)N;
            const float4* m4 = (const float4*)(mem + (size_t)(ok_cur ? n_cur : 0) * DDIM);
            ma = ok_cur ? m4[lane] : make_float4(0,0,0,0);
            mb = ok_cur ? m4[lane + 32] : make_float4(0,0,0,0);
            iv = ok_cur ? g_minv[n_cur] : 0.f;
        }
        float d = qa.x*cma.x + qa.y*cma.y + qa.z*cma.z + qa.w*cma.w
                + qb.x*cmb.x + qb.y*cmb.y + qb.z*cmb.z + qb.w*cmb.w;
        #pragma unroll
        for (int o = 16; o > 0; o >>= 1) d += __shfl_xor_sync(0xffffffffu, d, o);
        d *= civ;
        if (ok) {
            #pragma unroll
            for (int i = KTOP - 1; i >= 0; --i) {
                bool above = (d > sv[i]) || (d == sv[i] && n < si[i]);
                if (above) {
                    if (i < KTOP - 1) { sv[i + 1] = sv[i]; si[i + 1] = si[i]; }
                    sv[i] = d; si[i] = n;
                }
            }
        }
    }

    // ---- write scores + gather raw rows ----------------------------------
    #pragma unroll
    for (int r = 0; r < KTOP; ++r) {
        if (lane == 0)
            out[(size_t)B * KTOP * DDIM + (size_t)qi * KTOP + r] = sv[r];
        int n = si[r];
        if ((unsigned)n < (unsigned)N) {
            const float4* src = (const float4*)(mem + (size_t)n * DDIM);
            float4* dst = (float4*)(out + ((size_t)qi * KTOP + r) * DDIM);
            dst[lane]      = src[lane];
            dst[lane + 32] = src[lane + 32];
        }
    }
}

// ---------------- entry -----------------------------------------------------
extern "C" void kernel_launch(void* const* d_in, const int* in_sizes, int n_in,
                              void* d_out, int out_size) {
    const float* query = (const float*)d_in[0];
    const float* mem   = (const float*)d_in[1];
    float* out         = (float*)d_out;
    (void)n_in; (void)out_size;

    const int B = in_sizes[0] / DDIM;            // 2048
    const int N = in_sizes[1] / DDIM;            // 100000
    const int ntiles = (N + NT - 1) / NT;        // 782
    const int nrows_pad = ntiles * NT;           // 100096

    const int total_warps = nrows_pad + B;
    norm_kernel<<<(total_warps * 32 + 255) / 256, 256>>>(query, mem, B, N, nrows_pad);

    cudaFuncSetAttribute(gemm_topk_kernel,
                         cudaFuncAttributeMaxDynamicSharedMemorySize, SMEM_BYTES);
    dim3 grid(B / QT, NSPLIT);
    gemm_topk_kernel<<<grid, 256, SMEM_BYTES>>>(ntiles);

    rerank_kernel<<<(B + 7) / 8, 256>>>(query, mem, out, B, N);
}

// round 11
// speedup vs baseline: 1.5591x; 1.5591x over previous
#include <cuda_runtime.h>
#include <cuda_bf16.h>
#include <cuda_fp8.h>
#include <math.h>
#include <stdint.h>

// ---------------- problem constants ----------------------------------------
#define DDIM   256
#define KTOP   8
#define CDEP   4            // per-thread per-row candidate depth (gemm)
#define CPS    32           // candidates per (query, split) = 8 slots x CDEP
#define CTOP   24           // merged candidates re-ranked exactly in fp32
#define QT     128          // queries per CTA (M)
#define NT     128          // memory rows per tile (N)
#define NSPLIT 18           // 16 x 18 = 288 CTAs; 2 CTA/SM -> one wave of 296
#define NPAD_MAX 100096
#define BQ_MAX   2048

// ---------------- device scratch (static, no dynamic alloc) ----------------
__device__ uint8_t g_qe[(size_t)BQ_MAX   * DDIM];   // normalized queries, e4m3 x16
__device__ uint8_t g_me[(size_t)NPAD_MAX * DDIM];   // normalized memory,  e4m3 x16
__device__ float   g_minv[NPAD_MAX];                // 1/max(||m||, eps)
__device__ float g_cand_val[(size_t)BQ_MAX * NSPLIT * CPS];
__device__ int   g_cand_idx[(size_t)BQ_MAX * NSPLIT * CPS];

// ---------------- PTX helpers (plain-target instructions only) -------------
__device__ __forceinline__ uint32_t smem_to_u32(const void* p) {
    uint32_t a;
    asm("{ .reg .u64 t; cvta.to.shared.u64 t, %1; cvt.u32.u64 %0, t; }"
        : "=r"(a) : "l"(p));
    return a;
}

#define CP_ASYNC16(s, g) \
    asm volatile("cp.async.cg.shared.global [%0], [%1], 16;" :: "r"(s), "l"(g))
#define CP_COMMIT() asm volatile("cp.async.commit_group;" ::: "memory")
#define CP_WAIT(n)  asm volatile("cp.async.wait_group %0;" :: "n"(n) : "memory")

__device__ __forceinline__ void ldsm4(uint32_t* r, uint32_t a) {
    asm volatile("ldmatrix.sync.aligned.m8n8.x4.shared.b16 {%0,%1,%2,%3}, [%4];"
        : "=r"(r[0]), "=r"(r[1]), "=r"(r[2]), "=r"(r[3]) : "r"(a));
}

// fp8 e4m3 MMA: D(16x8,f32) += A(16x32) * B(32x8)
__device__ __forceinline__ void mma16832(float* d, const uint32_t* a,
                                         uint32_t b0, uint32_t b1) {
    asm volatile(
        "mma.sync.aligned.m16n8k32.row.col.f32.e4m3.e4m3.f32 "
        "{%0,%1,%2,%3}, {%4,%5,%6,%7}, {%8,%9}, {%0,%1,%2,%3};"
        : "+f"(d[0]), "+f"(d[1]), "+f"(d[2]), "+f"(d[3])
        : "r"(a[0]), "r"(a[1]), "r"(a[2]), "r"(a[3]), "r"(b0), "r"(b1));
}

// ---------------- fused normalize: mem + query rows, one launch ------------
__device__ __forceinline__ uint32_t pack_e4m3x4(float x, float y, float z, float w) {
    __nv_fp8x4_e4m3 p(make_float4(x, y, z, w));
    return *reinterpret_cast<uint32_t*>(&p);
}

__global__ void norm_kernel(const float* __restrict__ q,
                            const float* __restrict__ m,
                            int B, int Nvalid, int Ntot) {
    const int warp = (blockIdx.x * blockDim.x + threadIdx.x) >> 5;
    const int lane = threadIdx.x & 31;
    const bool is_mem = warp < Ntot;
    if (!is_mem && warp - Ntot >= B) return;

    const int row = is_mem ? warp : warp - Ntot;
    if (is_mem && row >= Nvalid) {   // zero pad rows
        uint32_t* dst = (uint32_t*)(g_me + (size_t)row * DDIM);
        dst[lane] = 0u; dst[lane + 32] = 0u;
        if (lane == 0) g_minv[row] = 0.f;
        return;
    }
    const float* in = is_mem ? m : q;
    uint32_t* dst = (uint32_t*)((is_mem ? g_me : g_qe) + (size_t)row * DDIM);

    const float4* src = (const float4*)(in + (size_t)row * DDIM);
    float4 a = src[lane];
    float4 b = src[lane + 32];
    float ss = a.x*a.x + a.y*a.y + a.z*a.z + a.w*a.w
             + b.x*b.x + b.y*b.y + b.z*b.z + b.w*b.w;
    #pragma unroll
    for (int o = 16; o > 0; o >>= 1) ss += __shfl_xor_sync(0xffffffffu, ss, o);
    float invn = 1.0f / fmaxf(sqrtf(ss), 1e-12f);
    float inv  = 16.0f * invn;                    // x16 centers e4m3 range
    dst[lane]      = pack_e4m3x4(a.x*inv, a.y*inv, a.z*inv, a.w*inv);
    dst[lane + 32] = pack_e4m3x4(b.x*inv, b.y*inv, b.z*inv, b.w*inv);
    if (is_mem && lane == 0) g_minv[row] = invn;
}

// ---------------- top-L insertion (ascending, v[0]=min) --------------------
template <int L>
__device__ __forceinline__ void insL(float s, int n, float* v, int* id) {
    #pragma unroll
    for (int i = 0; i < L; ++i) {
        if (s > v[i]) {
            bool up = (i < L - 1) && (s > v[i + 1]);
            float nv = up ? v[i + 1] : s;
            int   ni = up ? id[i + 1] : n;
            v[i] = nv; id[i] = ni;
        }
    }
}

template <int L>
__device__ __forceinline__ void insL_tie(float s, int n, float* v, int* id) {
    #pragma unroll
    for (int i = 0; i < L; ++i) {
        bool better = (s > v[i]) || (s == v[i] && n < id[i]);
        if (better) {
            bool up = (i < L - 1) && ((s > v[i + 1]) || (s == v[i + 1] && n < id[i + 1]));
            float nv = up ? v[i + 1] : s;
            int   ni = up ? id[i + 1] : n;
            v[i] = nv; id[i] = ni;
        }
    }
}

// ---------------- fused fp8 QMMA GEMM + fragment-direct top-4 --------------
// smem: A resident 32KB + B double buffer 2x32KB  -> 2 CTAs/SM
#define SA    0
#define SB0   32768
#define SB1   65536
#define SMEM_BYTES 98304

// load one 128-row x 256-byte fp8 tile with xor-swizzle (16B granules)
__device__ __forceinline__ void load_tile8(uint32_t sbuf, const uint8_t* g, int tid) {
    #pragma unroll
    for (int j = 0; j < 8; ++j) {
        int c_lin = j * 256 + tid;          // 2048 16B chunks
        int row = c_lin >> 4;
        int c   = c_lin & 15;
        uint32_t sw = (uint32_t)(((c ^ row) & 7) | (c & 8));
        CP_ASYNC16(sbuf + (uint32_t)(row * 256) + (sw << 4),
                   g + (size_t)row * 256 + c * 16);
    }
}

__global__ __launch_bounds__(256, 2)
void gemm_topk_kernel(int ntiles) {
    extern __shared__ __align__(16) char smem[];
    const uint32_t sb = smem_to_u32(smem);
    const int tid  = threadIdx.x, lane = tid & 31, wid = tid >> 5;
    const int wm   = wid >> 1, wn = wid & 1;            // 4 x 2 warp grid
    const int m0   = blockIdx.x * QT, split = blockIdx.y;
    const int t0   = (split * ntiles) / NSPLIT;
    const int t1   = ((split + 1) * ntiles) / NSPLIT;

    const int rA = wm * 32 + (lane & 15);
    const int rB = wn * 64 + (lane & 15);
    const int ch = lane >> 4;
    const int xA = rA & 7, xB = rB & 7;

    // per-thread candidates: 4 owned query-rows x depth-4 (ascending)
    float cv[4][CDEP]; int ci[4][CDEP];
    #pragma unroll
    for (int r = 0; r < 4; ++r)
        #pragma unroll
        for (int i = 0; i < CDEP; ++i) { cv[r][i] = -3e38f; ci[r][i] = 0x7fffffff; }

    load_tile8(sb + SA, g_qe + (size_t)m0 * DDIM, tid);
    load_tile8(sb + SB0, g_me + (size_t)t0 * NT * DDIM, tid);
    CP_COMMIT();

    const int colbase = wn * 64 + ((lane & 3) << 1);

    for (int t = t0; t < t1; ++t) {
        const int p = (t - t0) & 1;
        const uint32_t bufB = sb + (p ? SB1 : SB0);

        CP_WAIT(0);
        __syncthreads();
        if (t + 1 < t1) {   // prefetch next B tile into the other buffer
            load_tile8(sb + (p ? SB0 : SB1), g_me + (size_t)(t + 1) * NT * DDIM, tid);
            CP_COMMIT();
        }

        float acc[2][8][4];
        #pragma unroll
        for (int mi = 0; mi < 2; ++mi)
            #pragma unroll
            for (int nj = 0; nj < 8; ++nj)
                #pragma unroll
                for (int e = 0; e < 4; ++e) acc[mi][nj][e] = 0.f;

        const uint32_t bufA = sb + SA;
        #pragma unroll
        for (int ks = 0; ks < 8; ++ks) {
            const int c = ks * 2 + ch;
            const uint32_t swA = (uint32_t)((((c ^ xA) & 7) | (c & 8)) << 4);
            const uint32_t swB = (uint32_t)((((c ^ xB) & 7) | (c & 8)) << 4);
            uint32_t a0[4], a1[4], bfr[4][4];
            ldsm4(a0, bufA + (uint32_t)(rA * 256) + swA);
            ldsm4(a1, bufA + (uint32_t)((rA + 16) * 256) + swA);
            #pragma unroll
            for (int g = 0; g < 4; ++g)
                ldsm4(bfr[g], bufB + (uint32_t)((rB + g * 16) * 256) + swB);
            #pragma unroll
            for (int g = 0; g < 4; ++g) {
                mma16832(acc[0][2*g],     a0, bfr[g][0], bfr[g][2]);
                mma16832(acc[0][2*g + 1], a0, bfr[g][1], bfr[g][3]);
                mma16832(acc[1][2*g],     a1, bfr[g][0], bfr[g][2]);
                mma16832(acc[1][2*g + 1], a1, bfr[g][1], bfr[g][3]);
            }
        }

        // ---- fragment-direct scan: insert owned scores into top-4 lists ---
        const int nb = t * NT + colbase;
        #pragma unroll
        for (int mi = 0; mi < 2; ++mi)
            #pragma unroll
            for (int nj = 0; nj < 8; ++nj) {
                const int n0 = nb + nj * 8;
                float* a = acc[mi][nj];
                if (a[0] > cv[2*mi][0])     insL<CDEP>(a[0], n0,     cv[2*mi],     ci[2*mi]);
                if (a[1] > cv[2*mi][0])     insL<CDEP>(a[1], n0 + 1, cv[2*mi],     ci[2*mi]);
                if (a[2] > cv[2*mi + 1][0]) insL<CDEP>(a[2], n0,     cv[2*mi + 1], ci[2*mi + 1]);
                if (a[3] > cv[2*mi + 1][0]) insL<CDEP>(a[3], n0 + 1, cv[2*mi + 1], ci[2*mi + 1]);
            }
    }

    // ---- write candidates: slot = wn*4 + (lane&3), CDEP entries each ------
    {
        const int er   = wm * 32 + (lane >> 2);
        const int slot = wn * 4 + (lane & 3);
        #pragma unroll
        for (int r = 0; r < 4; ++r) {
            const int qrow = m0 + er + (r >> 1) * 16 + (r & 1) * 8;
            const size_t base = ((size_t)qrow * NSPLIT + split) * CPS + slot * CDEP;
            #pragma unroll
            for (int i = 0; i < CDEP; ++i) {
                g_cand_val[base + i] = cv[r][i];
                g_cand_idx[base + i] = ci[r][i];
            }
        }
    }
}

// ---------------- rerank: phase-split selection + pipelined exact scoring --
#define CANDN (NSPLIT * CPS)   // 576
#define CSLOT (CANDN / 32)     // 18
#define LDEP  8                // per-lane sorted depth (union 256 >= any top-24)

__global__ void rerank_kernel(const float* __restrict__ q,
                              const float* __restrict__ mem,
                              float* __restrict__ out, int B, int N) {
    const int lane = threadIdx.x & 31;
    const int w    = threadIdx.x >> 5;
    const int qi   = blockIdx.x * 8 + w;
    if (qi >= B) return;

    __shared__ int s_idx[8][CTOP];

    // ---- phase A: per-lane sorted top-8, then CTOP pop-max extractions ----
    {
        float hv[LDEP]; int hi[LDEP];
        #pragma unroll
        for (int i = 0; i < LDEP; ++i) { hv[i] = -3e38f; hi[i] = 0x7fffffff; }
        const size_t cb = (size_t)qi * CANDN;
        #pragma unroll
        for (int j = 0; j < CSLOT; ++j) {
            int c = lane + j * 32;
            float s = g_cand_val[cb + c];
            int   n = g_cand_idx[cb + c];
            bool better0 = (s > hv[0]) || (s == hv[0] && n < hi[0]);
            if (better0) insL_tie<LDEP>(s, n, hv, hi);
        }
        #pragma unroll 1
        for (int r = 0; r < CTOP; ++r) {
            float mv = hv[LDEP - 1]; int mi = hi[LDEP - 1];
            float bv = mv; int bi = mi;
            #pragma unroll
            for (int o = 16; o > 0; o >>= 1) {
                float ov = __shfl_xor_sync(0xffffffffu, bv, o);
                int   oi = __shfl_xor_sync(0xffffffffu, bi, o);
                if (ov > bv || (ov == bv && oi < bi)) { bv = ov; bi = oi; }
            }
            if (mv == bv && mi == bi) {   // winner lane pops its max
                #pragma unroll
                for (int i = LDEP - 1; i > 0; --i) { hv[i] = hv[i - 1]; hi[i] = hi[i - 1]; }
                hv[0] = -3e38f; hi[0] = 0x7fffffff;
            }
            if (lane == 0) s_idx[w][r] = bi;
        }
        __syncwarp();
    }

    // ---- normalized query in registers -----------------------------------
    const float4* q4 = (const float4*)(q + (size_t)qi * DDIM);
    float4 qa = q4[lane], qb = q4[lane + 32];
    float qs = qa.x*qa.x + qa.y*qa.y + qa.z*qa.z + qa.w*qa.w
             + qb.x*qb.x + qb.y*qb.y + qb.z*qb.z + qb.w*qb.w;
    #pragma unroll
    for (int o = 16; o > 0; o >>= 1) qs += __shfl_xor_sync(0xffffffffu, qs, o);
    float qn = fmaxf(sqrtf(qs), 1e-12f);
    qa.x /= qn; qa.y /= qn; qa.z /= qn; qa.w /= qn;
    qb.x /= qn; qb.y /= qn; qb.z /= qn; qb.w /= qn;

    // ---- phase B: pipelined exact fp32 scoring of the CTOP candidates -----
    float sv[KTOP]; int si[KTOP];
    #pragma unroll
    for (int i = 0; i < KTOP; ++i) { sv[i] = -3e38f; si[i] = 0x7fffffff; }

    int   n_cur  = s_idx[w][0];
    bool  ok_cur = (unsigned)n_cur < (unsigned)N;
    float4 ma, mb; float iv;
    {
        const float4* m4 = (const float4*)(mem + (size_t)(ok_cur ? n_cur : 0) * DDIM);
        ma = ok_cur ? m4[lane] : make_float4(0,0,0,0);
        mb = ok_cur ? m4[lane + 32] : make_float4(0,0,0,0);
        iv = ok_cur ? g_minv[n_cur] : 0.f;
    }

    #pragma unroll 1
    for (int c = 0; c < CTOP; ++c) {
        float4 cma = ma, cmb = mb; float civ = iv;
        const int  n  = n_cur;
        const bool ok = ok_cur;
        if (c + 1 < CTOP) {          // issue next loads before the reduction
            n_cur  = s_idx[w][c + 1];
            ok_cur = (unsigned)n_cur < (unsigned)N;
            const float4* m4 = (const float4*)(mem + (size_t)(ok_cur ? n_cur : 0) * DDIM);
            ma = ok_cur ? m4[lane] : make_float4(0,0,0,0);
            mb = ok_cur ? m4[lane + 32] : make_float4(0,0,0,0);
            iv = ok_cur ? g_minv[n_cur] : 0.f;
        }
        float d = qa.x*cma.x + qa.y*cma.y + qa.z*cma.z + qa.w*cma.w
                + qb.x*cmb.x + qb.y*cmb.y + qb.z*cmb.z + qb.w*cmb.w;
        #pragma unroll
        for (int o = 16; o > 0; o >>= 1) d += __shfl_xor_sync(0xffffffffu, d, o);
        d *= civ;
        if (ok) {
            #pragma unroll
            for (int i = KTOP - 1; i >= 0; --i) {
                bool above = (d > sv[i]) || (d == sv[i] && n < si[i]);
                if (above) {
                    if (i < KTOP - 1) { sv[i + 1] = sv[i]; si[i + 1] = si[i]; }
                    sv[i] = d; si[i] = n;
                }
            }
        }
    }

    // ---- write scores + gather raw rows ----------------------------------
    #pragma unroll
    for (int r = 0; r < KTOP; ++r) {
        if (lane == 0)
            out[(size_t)B * KTOP * DDIM + (size_t)qi * KTOP + r] = sv[r];
        int n = si[r];
        if ((unsigned)n < (unsigned)N) {
            const float4* src = (const float4*)(mem + (size_t)n * DDIM);
            float4* dst = (float4*)(out + ((size_t)qi * KTOP + r) * DDIM);
            dst[lane]      = src[lane];
            dst[lane + 32] = src[lane + 32];
        }
    }
}

// ---------------- entry -----------------------------------------------------
extern "C" void kernel_launch(void* const* d_in, const int* in_sizes, int n_in,
                              void* d_out, int out_size) {
    const float* query = (const float*)d_in[0];
    const float* mem   = (const float*)d_in[1];
    float* out         = (float*)d_out;
    (void)n_in; (void)out_size;

    const int B = in_sizes[0] / DDIM;            // 2048
    const int N = in_sizes[1] / DDIM;            // 100000
    const int ntiles = (N + NT - 1) / NT;        // 782
    const int nrows_pad = ntiles * NT;           // 100096

    const int total_warps = nrows_pad + B;
    norm_kernel<<<(total_warps * 32 + 255) / 256, 256>>>(query, mem, B, N, nrows_pad);

    cudaFuncSetAttribute(gemm_topk_kernel,
                         cudaFuncAttributeMaxDynamicSharedMemorySize, SMEM_BYTES);
    dim3 grid(B / QT, NSPLIT);
    gemm_topk_kernel<<<grid, 256, SMEM_BYTES>>>(ntiles);

    rerank_kernel<<<(B + 7) / 8, 256>>>(query, mem, out, B, N);
}

// round 12
// speedup vs baseline: 1.5713x; 1.0078x over previous
#include <cuda_runtime.h>
#include <cuda_bf16.h>
#include <cuda_fp8.h>
#include <math.h>
#include <stdint.h>

// ---------------- problem constants ----------------------------------------
#define DDIM   256
#define KTOP   8
#define CDEP   4            // per-thread per-row candidate depth (gemm)
#define CPS    32           // candidates per (query, split) = 8 slots x CDEP
#define CTOP   24           // merged candidates re-ranked exactly in fp32
#define CHALF  (CTOP / 2)   // per-warp share in rerank phase B
#define QT     128          // queries per CTA (M)
#define NT     128          // memory rows per tile (N)
#define NSPLIT 18           // 16 x 18 = 288 CTAs; 2 CTA/SM -> one wave of 296
#define NPAD_MAX 100096
#define BQ_MAX   2048

// ---------------- device scratch (static, no dynamic alloc) ----------------
__device__ uint8_t g_qe[(size_t)BQ_MAX   * DDIM];   // normalized queries, e4m3 x16
__device__ uint8_t g_me[(size_t)NPAD_MAX * DDIM];   // normalized memory,  e4m3 x16
__device__ float   g_minv[NPAD_MAX];                // 1/max(||m||, eps)
__device__ float g_cand_val[(size_t)BQ_MAX * NSPLIT * CPS];
__device__ int   g_cand_idx[(size_t)BQ_MAX * NSPLIT * CPS];

// ---------------- PTX helpers (plain-target instructions only) -------------
__device__ __forceinline__ uint32_t smem_to_u32(const void* p) {
    uint32_t a;
    asm("{ .reg .u64 t; cvta.to.shared.u64 t, %1; cvt.u32.u64 %0, t; }"
        : "=r"(a) : "l"(p));
    return a;
}

#define CP_ASYNC16(s, g) \
    asm volatile("cp.async.cg.shared.global [%0], [%1], 16;" :: "r"(s), "l"(g))
#define CP_COMMIT() asm volatile("cp.async.commit_group;" ::: "memory")
#define CP_WAIT(n)  asm volatile("cp.async.wait_group %0;" :: "n"(n) : "memory")

__device__ __forceinline__ void ldsm4(uint32_t* r, uint32_t a) {
    asm volatile("ldmatrix.sync.aligned.m8n8.x4.shared.b16 {%0,%1,%2,%3}, [%4];"
        : "=r"(r[0]), "=r"(r[1]), "=r"(r[2]), "=r"(r[3]) : "r"(a));
}

// fp8 e4m3 MMA: D(16x8,f32) += A(16x32) * B(32x8)
__device__ __forceinline__ void mma16832(float* d, const uint32_t* a,
                                         uint32_t b0, uint32_t b1) {
    asm volatile(
        "mma.sync.aligned.m16n8k32.row.col.f32.e4m3.e4m3.f32 "
        "{%0,%1,%2,%3}, {%4,%5,%6,%7}, {%8,%9}, {%0,%1,%2,%3};"
        : "+f"(d[0]), "+f"(d[1]), "+f"(d[2]), "+f"(d[3])
        : "r"(a[0]), "r"(a[1]), "r"(a[2]), "r"(a[3]), "r"(b0), "r"(b1));
}

// ---------------- fused normalize: mem + query rows, one launch ------------
__device__ __forceinline__ uint32_t pack_e4m3x4(float x, float y, float z, float w) {
    __nv_fp8x4_e4m3 p(make_float4(x, y, z, w));
    return *reinterpret_cast<uint32_t*>(&p);
}

__global__ void norm_kernel(const float* __restrict__ q,
                            const float* __restrict__ m,
                            int B, int Nvalid, int Ntot) {
    const int warp = (blockIdx.x * blockDim.x + threadIdx.x) >> 5;
    const int lane = threadIdx.x & 31;
    const bool is_mem = warp < Ntot;
    if (!is_mem && warp - Ntot >= B) return;

    const int row = is_mem ? warp : warp - Ntot;
    if (is_mem && row >= Nvalid) {   // zero pad rows
        uint32_t* dst = (uint32_t*)(g_me + (size_t)row * DDIM);
        dst[lane] = 0u; dst[lane + 32] = 0u;
        if (lane == 0) g_minv[row] = 0.f;
        return;
    }
    const float* in = is_mem ? m : q;
    uint32_t* dst = (uint32_t*)((is_mem ? g_me : g_qe) + (size_t)row * DDIM);

    const float4* src = (const float4*)(in + (size_t)row * DDIM);
    float4 a = src[lane];
    float4 b = src[lane + 32];
    float ss = a.x*a.x + a.y*a.y + a.z*a.z + a.w*a.w
             + b.x*b.x + b.y*b.y + b.z*b.z + b.w*b.w;
    #pragma unroll
    for (int o = 16; o > 0; o >>= 1) ss += __shfl_xor_sync(0xffffffffu, ss, o);
    float invn = 1.0f / fmaxf(sqrtf(ss), 1e-12f);
    float inv  = 16.0f * invn;                    // x16 centers e4m3 range
    dst[lane]      = pack_e4m3x4(a.x*inv, a.y*inv, a.z*inv, a.w*inv);
    dst[lane + 32] = pack_e4m3x4(b.x*inv, b.y*inv, b.z*inv, b.w*inv);
    if (is_mem && lane == 0) g_minv[row] = invn;
}

// ---------------- top-L insertion (ascending, v[0]=min) --------------------
template <int L>
__device__ __forceinline__ void insL(float s, int n, float* v, int* id) {
    #pragma unroll
    for (int i = 0; i < L; ++i) {
        if (s > v[i]) {
            bool up = (i < L - 1) && (s > v[i + 1]);
            float nv = up ? v[i + 1] : s;
            int   ni = up ? id[i + 1] : n;
            v[i] = nv; id[i] = ni;
        }
    }
}

template <int L>
__device__ __forceinline__ void insL_tie(float s, int n, float* v, int* id) {
    #pragma unroll
    for (int i = 0; i < L; ++i) {
        bool better = (s > v[i]) || (s == v[i] && n < id[i]);
        if (better) {
            bool up = (i < L - 1) && ((s > v[i + 1]) || (s == v[i + 1] && n < id[i + 1]));
            float nv = up ? v[i + 1] : s;
            int   ni = up ? id[i + 1] : n;
            v[i] = nv; id[i] = ni;
        }
    }
}

// descending top-8 insertion with lower-index tie-break (sv[0] = best)
__device__ __forceinline__ void ins_desc8(float d, int n, float* sv, int* si) {
    #pragma unroll
    for (int i = KTOP - 1; i >= 0; --i) {
        bool above = (d > sv[i]) || (d == sv[i] && n < si[i]);
        if (above) {
            if (i < KTOP - 1) { sv[i + 1] = sv[i]; si[i + 1] = si[i]; }
            sv[i] = d; si[i] = n;
        }
    }
}

// ---------------- fused fp8 QMMA GEMM + fragment-direct top-4 --------------
// smem: A resident 32KB + B double buffer 2x32KB  -> 2 CTAs/SM
#define SA    0
#define SB0   32768
#define SB1   65536
#define SMEM_BYTES 98304

// load one 128-row x 256-byte fp8 tile with xor-swizzle (16B granules)
__device__ __forceinline__ void load_tile8(uint32_t sbuf, const uint8_t* g, int tid) {
    #pragma unroll
    for (int j = 0; j < 8; ++j) {
        int c_lin = j * 256 + tid;          // 2048 16B chunks
        int row = c_lin >> 4;
        int c   = c_lin & 15;
        uint32_t sw = (uint32_t)(((c ^ row) & 7) | (c & 8));
        CP_ASYNC16(sbuf + (uint32_t)(row * 256) + (sw << 4),
                   g + (size_t)row * 256 + c * 16);
    }
}

__global__ __launch_bounds__(256, 2)
void gemm_topk_kernel(int ntiles) {
    extern __shared__ __align__(16) char smem[];
    const uint32_t sb = smem_to_u32(smem);
    const int tid  = threadIdx.x, lane = tid & 31, wid = tid >> 5;
    const int wm   = wid >> 1, wn = wid & 1;            // 4 x 2 warp grid
    const int m0   = blockIdx.x * QT, split = blockIdx.y;
    const int t0   = (split * ntiles) / NSPLIT;
    const int t1   = ((split + 1) * ntiles) / NSPLIT;

    const int rA = wm * 32 + (lane & 15);
    const int rB = wn * 64 + (lane & 15);
    const int ch = lane >> 4;
    const int xA = rA & 7, xB = rB & 7;

    // per-thread candidates: 4 owned query-rows x depth-4 (ascending)
    float cv[4][CDEP]; int ci[4][CDEP];
    #pragma unroll
    for (int r = 0; r < 4; ++r)
        #pragma unroll
        for (int i = 0; i < CDEP; ++i) { cv[r][i] = -3e38f; ci[r][i] = 0x7fffffff; }

    load_tile8(sb + SA, g_qe + (size_t)m0 * DDIM, tid);
    load_tile8(sb + SB0, g_me + (size_t)t0 * NT * DDIM, tid);
    CP_COMMIT();

    const int colbase = wn * 64 + ((lane & 3) << 1);

    for (int t = t0; t < t1; ++t) {
        const int p = (t - t0) & 1;
        const uint32_t bufB = sb + (p ? SB1 : SB0);

        CP_WAIT(0);
        __syncthreads();
        if (t + 1 < t1) {   // prefetch next B tile into the other buffer
            load_tile8(sb + (p ? SB0 : SB1), g_me + (size_t)(t + 1) * NT * DDIM, tid);
            CP_COMMIT();
        }

        float acc[2][8][4];
        #pragma unroll
        for (int mi = 0; mi < 2; ++mi)
            #pragma unroll
            for (int nj = 0; nj < 8; ++nj)
                #pragma unroll
                for (int e = 0; e < 4; ++e) acc[mi][nj][e] = 0.f;

        const uint32_t bufA = sb + SA;
        #pragma unroll
        for (int ks = 0; ks < 8; ++ks) {
            const int c = ks * 2 + ch;
            const uint32_t swA = (uint32_t)((((c ^ xA) & 7) | (c & 8)) << 4);
            const uint32_t swB = (uint32_t)((((c ^ xB) & 7) | (c & 8)) << 4);
            uint32_t a0[4], a1[4], bfr[4][4];
            ldsm4(a0, bufA + (uint32_t)(rA * 256) + swA);
            ldsm4(a1, bufA + (uint32_t)((rA + 16) * 256) + swA);
            #pragma unroll
            for (int g = 0; g < 4; ++g)
                ldsm4(bfr[g], bufB + (uint32_t)((rB + g * 16) * 256) + swB);
            #pragma unroll
            for (int g = 0; g < 4; ++g) {
                mma16832(acc[0][2*g],     a0, bfr[g][0], bfr[g][2]);
                mma16832(acc[0][2*g + 1], a0, bfr[g][1], bfr[g][3]);
                mma16832(acc[1][2*g],     a1, bfr[g][0], bfr[g][2]);
                mma16832(acc[1][2*g + 1], a1, bfr[g][1], bfr[g][3]);
            }
        }

        // ---- fragment-direct scan: insert owned scores into top-4 lists ---
        const int nb = t * NT + colbase;
        #pragma unroll
        for (int mi = 0; mi < 2; ++mi)
            #pragma unroll
            for (int nj = 0; nj < 8; ++nj) {
                const int n0 = nb + nj * 8;
                float* a = acc[mi][nj];
                if (a[0] > cv[2*mi][0])     insL<CDEP>(a[0], n0,     cv[2*mi],     ci[2*mi]);
                if (a[1] > cv[2*mi][0])     insL<CDEP>(a[1], n0 + 1, cv[2*mi],     ci[2*mi]);
                if (a[2] > cv[2*mi + 1][0]) insL<CDEP>(a[2], n0,     cv[2*mi + 1], ci[2*mi + 1]);
                if (a[3] > cv[2*mi + 1][0]) insL<CDEP>(a[3], n0 + 1, cv[2*mi + 1], ci[2*mi + 1]);
            }
    }

    // ---- write candidates: slot = wn*4 + (lane&3), CDEP entries each ------
    {
        const int er   = wm * 32 + (lane >> 2);
        const int slot = wn * 4 + (lane & 3);
        #pragma unroll
        for (int r = 0; r < 4; ++r) {
            const int qrow = m0 + er + (r >> 1) * 16 + (r & 1) * 8;
            const size_t base = ((size_t)qrow * NSPLIT + split) * CPS + slot * CDEP;
            #pragma unroll
            for (int i = 0; i < CDEP; ++i) {
                g_cand_val[base + i] = cv[r][i];
                g_cand_idx[base + i] = ci[r][i];
            }
        }
    }
}

// ---------------- rerank v2: 2 warps/query, split exact scoring ------------
#define CANDN (NSPLIT * CPS)   // 576
#define CSLOT (CANDN / 32)     // 18
#define LDEP  8                // per-lane sorted depth (union 256 >= any top-24)
#define QPB   4                // queries per block (8 warps = 2 per query)

__global__ void rerank_kernel(const float* __restrict__ q,
                              const float* __restrict__ mem,
                              float* __restrict__ out, int B, int N) {
    const int lane = threadIdx.x & 31;
    const int w    = threadIdx.x >> 5;
    const int half = w & 1;
    const int ql   = w >> 1;                  // 0..3 local query
    const int qi   = blockIdx.x * QPB + ql;
    const bool act = qi < B;

    __shared__ int   s_idx[QPB][CTOP];
    __shared__ float s_mv[QPB][2][KTOP];
    __shared__ int   s_mi[QPB][2][KTOP];
    __shared__ float s_fv[QPB][KTOP];
    __shared__ int   s_fi[QPB][KTOP];

    // ---- phase A (even warp per query): candidate selection ---------------
    if (act && half == 0) {
        float hv[LDEP]; int hi[LDEP];
        #pragma unroll
        for (int i = 0; i < LDEP; ++i) { hv[i] = -3e38f; hi[i] = 0x7fffffff; }
        const size_t cb = (size_t)qi * CANDN;
        #pragma unroll
        for (int j = 0; j < CSLOT; ++j) {
            int c = lane + j * 32;
            float s = g_cand_val[cb + c];
            int   n = g_cand_idx[cb + c];
            bool better0 = (s > hv[0]) || (s == hv[0] && n < hi[0]);
            if (better0) insL_tie<LDEP>(s, n, hv, hi);
        }
        #pragma unroll 1
        for (int r = 0; r < CTOP; ++r) {
            float mv = hv[LDEP - 1]; int mi = hi[LDEP - 1];
            float bv = mv; int bi = mi;
            #pragma unroll
            for (int o = 16; o > 0; o >>= 1) {
                float ov = __shfl_xor_sync(0xffffffffu, bv, o);
                int   oi = __shfl_xor_sync(0xffffffffu, bi, o);
                if (ov > bv || (ov == bv && oi < bi)) { bv = ov; bi = oi; }
            }
            if (mv == bv && mi == bi) {   // winner lane pops its max
                #pragma unroll
                for (int i = LDEP - 1; i > 0; --i) { hv[i] = hv[i - 1]; hi[i] = hi[i - 1]; }
                hv[0] = -3e38f; hi[0] = 0x7fffffff;
            }
            if (lane == 0) s_idx[ql][r] = bi;
        }
    }
    __syncthreads();

    // ---- normalized query in registers (both warps) -----------------------
    const float4* q4 = (const float4*)(q + (size_t)(act ? qi : 0) * DDIM);
    float4 qa = q4[lane], qb = q4[lane + 32];
    float qs = qa.x*qa.x + qa.y*qa.y + qa.z*qa.z + qa.w*qa.w
             + qb.x*qb.x + qb.y*qb.y + qb.z*qb.z + qb.w*qb.w;
    #pragma unroll
    for (int o = 16; o > 0; o >>= 1) qs += __shfl_xor_sync(0xffffffffu, qs, o);
    float qn = fmaxf(sqrtf(qs), 1e-12f);
    qa.x /= qn; qa.y /= qn; qa.z /= qn; qa.w /= qn;
    qb.x /= qn; qb.y /= qn; qb.z /= qn; qb.w /= qn;

    // ---- phase B: each warp exactly scores its 12 candidates --------------
    float sv[KTOP]; int si[KTOP];
    #pragma unroll
    for (int i = 0; i < KTOP; ++i) { sv[i] = -3e38f; si[i] = 0x7fffffff; }

    {
        const int cbase = half * CHALF;
        int   n_cur  = act ? s_idx[ql][cbase] : 0x7fffffff;
        bool  ok_cur = (unsigned)n_cur < (unsigned)N;
        float4 ma, mb; float iv;
        {
            const float4* m4 = (const float4*)(mem + (size_t)(ok_cur ? n_cur : 0) * DDIM);
            ma = ok_cur ? m4[lane] : make_float4(0,0,0,0);
            mb = ok_cur ? m4[lane + 32] : make_float4(0,0,0,0);
            iv = ok_cur ? g_minv[n_cur] : 0.f;
        }
        #pragma unroll 1
        for (int c = 0; c < CHALF; ++c) {
            float4 cma = ma, cmb = mb; float civ = iv;
            const int  n  = n_cur;
            const bool ok = ok_cur;
            if (c + 1 < CHALF) {       // issue next loads before the reduction
                n_cur  = act ? s_idx[ql][cbase + c + 1] : 0x7fffffff;
                ok_cur = (unsigned)n_cur < (unsigned)N;
                const float4* m4 = (const float4*)(mem + (size_t)(ok_cur ? n_cur : 0) * DDIM);
                ma = ok_cur ? m4[lane] : make_float4(0,0,0,0);
                mb = ok_cur ? m4[lane + 32] : make_float4(0,0,0,0);
                iv = ok_cur ? g_minv[n_cur] : 0.f;
            }
            float d = qa.x*cma.x + qa.y*cma.y + qa.z*cma.z + qa.w*cma.w
                    + qb.x*cmb.x + qb.y*cmb.y + qb.z*cmb.z + qb.w*cmb.w;
            #pragma unroll
            for (int o = 16; o > 0; o >>= 1) d += __shfl_xor_sync(0xffffffffu, d, o);
            d *= civ;
            if (ok) ins_desc8(d, n, sv, si);
        }
        // publish this half's exact top-8 (warp-uniform; lane 0 writes)
        if (act && lane == 0) {
            #pragma unroll
            for (int i = 0; i < KTOP; ++i) { s_mv[ql][half][i] = sv[i]; s_mi[ql][half][i] = si[i]; }
        }
    }
    __syncthreads();

    // ---- merge the two exact top-8 lists (even warp, warp-uniform) --------
    if (act && half == 0) {
        float fv[KTOP]; int fi[KTOP];
        #pragma unroll
        for (int i = 0; i < KTOP; ++i) { fv[i] = -3e38f; fi[i] = 0x7fffffff; }
        #pragma unroll
        for (int j = 0; j < 2 * KTOP; ++j) {
            float d = s_mv[ql][j >> 3][j & 7];
            int   n = s_mi[ql][j >> 3][j & 7];
            if (n != 0x7fffffff) ins_desc8(d, n, fv, fi);
        }
        if (lane == 0) {
            #pragma unroll
            for (int i = 0; i < KTOP; ++i) { s_fv[ql][i] = fv[i]; s_fi[ql][i] = fi[i]; }
        }
    }
    __syncthreads();

    // ---- outputs: scores (even warp) + gather split across the pair -------
    if (act) {
        if (half == 0 && lane < KTOP)
            out[(size_t)B * KTOP * DDIM + (size_t)qi * KTOP + lane] = s_fv[ql][lane];
        #pragma unroll
        for (int r = 0; r < KTOP / 2; ++r) {
            const int rr = half * (KTOP / 2) + r;
            const int n  = s_fi[ql][rr];
            if ((unsigned)n < (unsigned)N) {
                const float4* src = (const float4*)(mem + (size_t)n * DDIM);
                float4* dst = (float4*)(out + ((size_t)qi * KTOP + rr) * DDIM);
                dst[lane]      = src[lane];
                dst[lane + 32] = src[lane + 32];
            }
        }
    }
}

// ---------------- entry -----------------------------------------------------
extern "C" void kernel_launch(void* const* d_in, const int* in_sizes, int n_in,
                              void* d_out, int out_size) {
    const float* query = (const float*)d_in[0];
    const float* mem   = (const float*)d_in[1];
    float* out         = (float*)d_out;
    (void)n_in; (void)out_size;

    const int B = in_sizes[0] / DDIM;            // 2048
    const int N = in_sizes[1] / DDIM;            // 100000
    const int ntiles = (N + NT - 1) / NT;        // 782
    const int nrows_pad = ntiles * NT;           // 100096

    const int total_warps = nrows_pad + B;
    norm_kernel<<<(total_warps * 32 + 255) / 256, 256>>>(query, mem, B, N, nrows_pad);

    cudaFuncSetAttribute(gemm_topk_kernel,
                         cudaFuncAttributeMaxDynamicSharedMemorySize, SMEM_BYTES);
    dim3 grid(B / QT, NSPLIT);
    gemm_topk_kernel<<<grid, 256, SMEM_BYTES>>>(ntiles);

    rerank_kernel<<<(B + QPB - 1) / QPB, 256>>>(query, mem, out, B, N);
}

// round 14
// speedup vs baseline: 1.5904x; 1.0121x over previous
#include <cuda_runtime.h>
#include <cuda_bf16.h>
#include <cuda_fp8.h>
#include <math.h>
#include <stdint.h>

// ---------------- problem constants ----------------------------------------
#define DDIM   256
#define KTOP   8
#define CDEP   4            // per-thread per-row candidate depth (gemm)
#define CPS    32           // candidates per (query, split) = 8 slots x CDEP
#define CHALF  12           // per-warp exact-rescore count (top-12 of its half)
#define QT     128          // queries per CTA (M)
#define NT     128          // memory rows per tile (N)
#define NSPLIT 18           // 16 x 18 = 288 CTAs; 2 CTA/SM -> one wave of 296
#define NPAD_MAX 100096
#define BQ_MAX   2048

// ---------------- device scratch (static, no dynamic alloc) ----------------
__device__ uint8_t g_qe[(size_t)BQ_MAX   * DDIM];   // normalized queries, e4m3 x16
__device__ uint8_t g_me[(size_t)NPAD_MAX * DDIM];   // normalized memory,  e4m3 x16
__device__ float   g_minv[NPAD_MAX];                // 1/max(||m||, eps)
__device__ float g_cand_val[(size_t)BQ_MAX * NSPLIT * CPS];
__device__ int   g_cand_idx[(size_t)BQ_MAX * NSPLIT * CPS];

// ---------------- PTX helpers (plain-target instructions only) -------------
__device__ __forceinline__ uint32_t smem_to_u32(const void* p) {
    uint32_t a;
    asm("{ .reg .u64 t; cvta.to.shared.u64 t, %1; cvt.u32.u64 %0, t; }"
        : "=r"(a) : "l"(p));
    return a;
}

#define CP_ASYNC16(s, g) \
    asm volatile("cp.async.cg.shared.global [%0], [%1], 16;" :: "r"(s), "l"(g))
#define CP_COMMIT() asm volatile("cp.async.commit_group;" ::: "memory")
#define CP_WAIT(n)  asm volatile("cp.async.wait_group %0;" :: "n"(n) : "memory")

__device__ __forceinline__ void ldsm4(uint32_t* r, uint32_t a) {
    asm volatile("ldmatrix.sync.aligned.m8n8.x4.shared.b16 {%0,%1,%2,%3}, [%4];"
        : "=r"(r[0]), "=r"(r[1]), "=r"(r[2]), "=r"(r[3]) : "r"(a));
}

// fp8 e4m3 MMA: D(16x8,f32) += A(16x32) * B(32x8)
__device__ __forceinline__ void mma16832(float* d, const uint32_t* a,
                                         uint32_t b0, uint32_t b1) {
    asm volatile(
        "mma.sync.aligned.m16n8k32.row.col.f32.e4m3.e4m3.f32 "
        "{%0,%1,%2,%3}, {%4,%5,%6,%7}, {%8,%9}, {%0,%1,%2,%3};"
        : "+f"(d[0]), "+f"(d[1]), "+f"(d[2]), "+f"(d[3])
        : "r"(a[0]), "r"(a[1]), "r"(a[2]), "r"(a[3]), "r"(b0), "r"(b1));
}

// ---------------- fused normalize: mem + query rows, one launch ------------
__device__ __forceinline__ uint32_t pack_e4m3x4(float x, float y, float z, float w) {
    __nv_fp8x4_e4m3 p(make_float4(x, y, z, w));
    return *reinterpret_cast<uint32_t*>(&p);
}

__global__ void norm_kernel(const float* __restrict__ q,
                            const float* __restrict__ m,
                            int B, int Nvalid, int Ntot) {
    const int warp = (blockIdx.x * blockDim.x + threadIdx.x) >> 5;
    const int lane = threadIdx.x & 31;
    const bool is_mem = warp < Ntot;
    if (!is_mem && warp - Ntot >= B) return;

    const int row = is_mem ? warp : warp - Ntot;
    if (is_mem && row >= Nvalid) {   // zero pad rows
        uint32_t* dst = (uint32_t*)(g_me + (size_t)row * DDIM);
        dst[lane] = 0u; dst[lane + 32] = 0u;
        if (lane == 0) g_minv[row] = 0.f;
        return;
    }
    const float* in = is_mem ? m : q;
    uint32_t* dst = (uint32_t*)((is_mem ? g_me : g_qe) + (size_t)row * DDIM);

    const float4* src = (const float4*)(in + (size_t)row * DDIM);
    float4 a = src[lane];
    float4 b = src[lane + 32];
    float ss = a.x*a.x + a.y*a.y + a.z*a.z + a.w*a.w
             + b.x*b.x + b.y*b.y + b.z*b.z + b.w*b.w;
    #pragma unroll
    for (int o = 16; o > 0; o >>= 1) ss += __shfl_xor_sync(0xffffffffu, ss, o);
    float invn = 1.0f / fmaxf(sqrtf(ss), 1e-12f);
    float inv  = 16.0f * invn;                    // x16 centers e4m3 range
    dst[lane]      = pack_e4m3x4(a.x*inv, a.y*inv, a.z*inv, a.w*inv);
    dst[lane + 32] = pack_e4m3x4(b.x*inv, b.y*inv, b.z*inv, b.w*inv);
    if (is_mem && lane == 0) g_minv[row] = invn;
}

// ---------------- top-L insertion (ascending, v[0]=min) --------------------
template <int L>
__device__ __forceinline__ void insL(float s, int n, float* v, int* id) {
    #pragma unroll
    for (int i = 0; i < L; ++i) {
        if (s > v[i]) {
            bool up = (i < L - 1) && (s > v[i + 1]);
            float nv = up ? v[i + 1] : s;
            int   ni = up ? id[i + 1] : n;
            v[i] = nv; id[i] = ni;
        }
    }
}

template <int L>
__device__ __forceinline__ void insL_tie(float s, int n, float* v, int* id) {
    #pragma unroll
    for (int i = 0; i < L; ++i) {
        bool better = (s > v[i]) || (s == v[i] && n < id[i]);
        if (better) {
            bool up = (i < L - 1) && ((s > v[i + 1]) || (s == v[i + 1] && n < id[i + 1]));
            float nv = up ? v[i + 1] : s;
            int   ni = up ? id[i + 1] : n;
            v[i] = nv; id[i] = ni;
        }
    }
}

// descending top-8 insertion with lower-index tie-break (sv[0] = best)
__device__ __forceinline__ void ins_desc8(float d, int n, float* sv, int* si) {
    #pragma unroll
    for (int i = KTOP - 1; i >= 0; --i) {
        bool above = (d > sv[i]) || (d == sv[i] && n < si[i]);
        if (above) {
            if (i < KTOP - 1) { sv[i + 1] = sv[i]; si[i + 1] = si[i]; }
            sv[i] = d; si[i] = n;
        }
    }
}

// ---------------- fused fp8 QMMA GEMM + fragment-direct top-4 --------------
// smem: A resident 32KB + B double buffer 2x32KB  -> 2 CTAs/SM
#define SA    0
#define SB0   32768
#define SB1   65536
#define SMEM_BYTES 98304

// load one 128-row x 256-byte fp8 tile with xor-swizzle (16B granules)
__device__ __forceinline__ void load_tile8(uint32_t sbuf, const uint8_t* g, int tid) {
    #pragma unroll
    for (int j = 0; j < 8; ++j) {
        int c_lin = j * 256 + tid;          // 2048 16B chunks
        int row = c_lin >> 4;
        int c   = c_lin & 15;
        uint32_t sw = (uint32_t)(((c ^ row) & 7) | (c & 8));
        CP_ASYNC16(sbuf + (uint32_t)(row * 256) + (sw << 4),
                   g + (size_t)row * 256 + c * 16);
    }
}

__global__ __launch_bounds__(256, 2)
void gemm_topk_kernel(int ntiles) {
    extern __shared__ __align__(16) char smem[];
    const uint32_t sb = smem_to_u32(smem);
    const int tid  = threadIdx.x, lane = tid & 31, wid = tid >> 5;
    const int wm   = wid >> 1, wn = wid & 1;            // 4 x 2 warp grid
    const int m0   = blockIdx.x * QT, split = blockIdx.y;
    const int t0   = (split * ntiles) / NSPLIT;
    const int t1   = ((split + 1) * ntiles) / NSPLIT;

    const int rA = wm * 32 + (lane & 15);
    const int rB = wn * 64 + (lane & 15);
    const int ch = lane >> 4;
    const int xA = rA & 7, xB = rB & 7;

    // per-thread candidates: 4 owned query-rows x depth-4 (ascending)
    float cv[4][CDEP]; int ci[4][CDEP];
    #pragma unroll
    for (int r = 0; r < 4; ++r)
        #pragma unroll
        for (int i = 0; i < CDEP; ++i) { cv[r][i] = -3e38f; ci[r][i] = 0x7fffffff; }

    load_tile8(sb + SA, g_qe + (size_t)m0 * DDIM, tid);
    load_tile8(sb + SB0, g_me + (size_t)t0 * NT * DDIM, tid);
    CP_COMMIT();

    const int colbase = wn * 64 + ((lane & 3) << 1);

    for (int t = t0; t < t1; ++t) {
        const int p = (t - t0) & 1;
        const uint32_t bufB = sb + (p ? SB1 : SB0);

        CP_WAIT(0);
        __syncthreads();
        if (t + 1 < t1) {   // prefetch next B tile into the other buffer
            load_tile8(sb + (p ? SB0 : SB1), g_me + (size_t)(t + 1) * NT * DDIM, tid);
            CP_COMMIT();
        }

        float acc[2][8][4];
        #pragma unroll
        for (int mi = 0; mi < 2; ++mi)
            #pragma unroll
            for (int nj = 0; nj < 8; ++nj)
                #pragma unroll
                for (int e = 0; e < 4; ++e) acc[mi][nj][e] = 0.f;

        const uint32_t bufA = sb + SA;
        #pragma unroll
        for (int ks = 0; ks < 8; ++ks) {
            const int c = ks * 2 + ch;
            const uint32_t swA = (uint32_t)((((c ^ xA) & 7) | (c & 8)) << 4);
            const uint32_t swB = (uint32_t)((((c ^ xB) & 7) | (c & 8)) << 4);
            uint32_t a0[4], a1[4], bfr[4][4];
            ldsm4(a0, bufA + (uint32_t)(rA * 256) + swA);
            ldsm4(a1, bufA + (uint32_t)((rA + 16) * 256) + swA);
            #pragma unroll
            for (int g = 0; g < 4; ++g)
                ldsm4(bfr[g], bufB + (uint32_t)((rB + g * 16) * 256) + swB);
            #pragma unroll
            for (int g = 0; g < 4; ++g) {
                mma16832(acc[0][2*g],     a0, bfr[g][0], bfr[g][2]);
                mma16832(acc[0][2*g + 1], a0, bfr[g][1], bfr[g][3]);
                mma16832(acc[1][2*g],     a1, bfr[g][0], bfr[g][2]);
                mma16832(acc[1][2*g + 1], a1, bfr[g][1], bfr[g][3]);
            }
        }

        // ---- fragment-direct scan: insert owned scores into top-4 lists ---
        const int nb = t * NT + colbase;
        #pragma unroll
        for (int mi = 0; mi < 2; ++mi)
            #pragma unroll
            for (int nj = 0; nj < 8; ++nj) {
                const int n0 = nb + nj * 8;
                float* a = acc[mi][nj];
                if (a[0] > cv[2*mi][0])     insL<CDEP>(a[0], n0,     cv[2*mi],     ci[2*mi]);
                if (a[1] > cv[2*mi][0])     insL<CDEP>(a[1], n0 + 1, cv[2*mi],     ci[2*mi]);
                if (a[2] > cv[2*mi + 1][0]) insL<CDEP>(a[2], n0,     cv[2*mi + 1], ci[2*mi + 1]);
                if (a[3] > cv[2*mi + 1][0]) insL<CDEP>(a[3], n0 + 1, cv[2*mi + 1], ci[2*mi + 1]);
            }
    }

    // ---- write candidates: slot = wn*4 + (lane&3), CDEP entries each ------
    {
        const int er   = wm * 32 + (lane >> 2);
        const int slot = wn * 4 + (lane & 3);
        #pragma unroll
        for (int r = 0; r < 4; ++r) {
            const int qrow = m0 + er + (r >> 1) * 16 + (r & 1) * 8;
            const size_t base = ((size_t)qrow * NSPLIT + split) * CPS + slot * CDEP;
            #pragma unroll
            for (int i = 0; i < CDEP; ++i) {
                g_cand_val[base + i] = cv[r][i];
                g_cand_idx[base + i] = ci[r][i];
            }
        }
    }
}

// ---------------- rerank v3: 2 fully-parallel warps per query --------------
// Each warp: selects top-12 (fp8 score) of its half of the splits, exactly
// rescored in fp32; exact 2x8 merge at the end.
#define CANDN   (NSPLIT * CPS)      // 576
#define CANDN_H (CANDN / 2)         // 288 per warp
#define CSLOT_H (CANDN_H / 32)      // 9
#define LDEP    8                   // per-lane sorted depth (256 >= any top-12)
#define QPB     4                   // queries per block (8 warps = 2 per query)

__global__ void rerank_kernel(const float* __restrict__ q,
                              const float* __restrict__ mem,
                              float* __restrict__ out, int B, int N) {
    const int lane = threadIdx.x & 31;
    const int w    = threadIdx.x >> 5;
    const int half = w & 1;
    const int ql   = w >> 1;                  // 0..3 local query
    const int qi   = blockIdx.x * QPB + ql;
    const bool act = qi < B;

    __shared__ float s_mv[QPB][2][KTOP];
    __shared__ int   s_mi[QPB][2][KTOP];
    __shared__ float s_fv[QPB][KTOP];
    __shared__ int   s_fi[QPB][KTOP];

    // ---- phase A: per-warp top-12 of its half (indices kept in registers) -
    int idx[CHALF];
    if (act) {
        float hv[LDEP]; int hi[LDEP];
        #pragma unroll
        for (int i = 0; i < LDEP; ++i) { hv[i] = -3e38f; hi[i] = 0x7fffffff; }
        const size_t cb = (size_t)qi * CANDN + (size_t)half * CANDN_H;
        #pragma unroll
        for (int j = 0; j < CSLOT_H; ++j) {
            int c = lane + j * 32;
            float s = g_cand_val[cb + c];
            int   n = g_cand_idx[cb + c];
            bool better0 = (s > hv[0]) || (s == hv[0] && n < hi[0]);
            if (better0) insL_tie<LDEP>(s, n, hv, hi);
        }
        #pragma unroll 1
        for (int r = 0; r < CHALF; ++r) {
            float mv = hv[LDEP - 1]; int mi = hi[LDEP - 1];
            float bv = mv; int bi = mi;
            #pragma unroll
            for (int o = 16; o > 0; o >>= 1) {
                float ov = __shfl_xor_sync(0xffffffffu, bv, o);
                int   oi = __shfl_xor_sync(0xffffffffu, bi, o);
                if (ov > bv || (ov == bv && oi < bi)) { bv = ov; bi = oi; }
            }
            if (mv == bv && mi == bi) {   // winner lane pops its max
                #pragma unroll
                for (int i = LDEP - 1; i > 0; --i) { hv[i] = hv[i - 1]; hi[i] = hi[i - 1]; }
                hv[0] = -3e38f; hi[0] = 0x7fffffff;
            }
            idx[r] = bi;                   // warp-uniform after reduction
        }
    } else {
        #pragma unroll
        for (int r = 0; r < CHALF; ++r) idx[r] = 0x7fffffff;
    }

    // ---- normalized query in registers ------------------------------------
    const float4* q4 = (const float4*)(q + (size_t)(act ? qi : 0) * DDIM);
    float4 qa = q4[lane], qb = q4[lane + 32];
    float qs = qa.x*qa.x + qa.y*qa.y + qa.z*qa.z + qa.w*qa.w
             + qb.x*qb.x + qb.y*qb.y + qb.z*qb.z + qb.w*qb.w;
    #pragma unroll
    for (int o = 16; o > 0; o >>= 1) qs += __shfl_xor_sync(0xffffffffu, qs, o);
    float qn = fmaxf(sqrtf(qs), 1e-12f);
    qa.x /= qn; qa.y /= qn; qa.z /= qn; qa.w /= qn;
    qb.x /= qn; qb.y /= qn; qb.z /= qn; qb.w /= qn;

    // ---- phase B: exact fp32 scoring of this warp's 12 candidates ---------
    float sv[KTOP]; int si[KTOP];
    #pragma unroll
    for (int i = 0; i < KTOP; ++i) { sv[i] = -3e38f; si[i] = 0x7fffffff; }

    {
        int   n_cur  = idx[0];
        bool  ok_cur = (unsigned)n_cur < (unsigned)N;
        float4 ma, mb; float iv;
        {
            const float4* m4 = (const float4*)(mem + (size_t)(ok_cur ? n_cur : 0) * DDIM);
            ma = ok_cur ? m4[lane] : make_float4(0,0,0,0);
            mb = ok_cur ? m4[lane + 32] : make_float4(0,0,0,0);
            iv = ok_cur ? g_minv[n_cur] : 0.f;
        }
        #pragma unroll 1
        for (int c = 0; c < CHALF; ++c) {
            float4 cma = ma, cmb = mb; float civ = iv;
            const int  n  = n_cur;
            const bool ok = ok_cur;
            if (c + 1 < CHALF) {       // issue next loads before the reduction
                n_cur  = idx[c + 1];
                ok_cur = (unsigned)n_cur < (unsigned)N;
                const float4* m4 = (const float4*)(mem + (size_t)(ok_cur ? n_cur : 0) * DDIM);
                ma = ok_cur ? m4[lane] : make_float4(0,0,0,0);
                mb = ok_cur ? m4[lane + 32] : make_float4(0,0,0,0);
                iv = ok_cur ? g_minv[n_cur] : 0.f;
            }
            float d = qa.x*cma.x + qa.y*cma.y + qa.z*cma.z + qa.w*cma.w
                    + qb.x*cmb.x + qb.y*cmb.y + qb.z*cmb.z + qb.w*cmb.w;
            #pragma unroll
            for (int o = 16; o > 0; o >>= 1) d += __shfl_xor_sync(0xffffffffu, d, o);
            d *= civ;
            if (ok) ins_desc8(d, n, sv, si);
        }
        // publish this half's exact top-8 (warp-uniform; lane 0 writes)
        if (act && lane == 0) {
            #pragma unroll
            for (int i = 0; i < KTOP; ++i) { s_mv[ql][half][i] = sv[i]; s_mi[ql][half][i] = si[i]; }
        }
    }
    __syncthreads();

    // ---- merge the two exact top-8 lists (even warp, warp-uniform) --------
    if (act && half == 0) {
        float fv[KTOP]; int fi[KTOP];
        #pragma unroll
        for (int i = 0; i < KTOP; ++i) { fv[i] = -3e38f; fi[i] = 0x7fffffff; }
        #pragma unroll
        for (int j = 0; j < 2 * KTOP; ++j) {
            float d = s_mv[ql][j >> 3][j & 7];
            int   n = s_mi[ql][j >> 3][j & 7];
            if (n != 0x7fffffff) ins_desc8(d, n, fv, fi);
        }
        if (lane == 0) {
            #pragma unroll
            for (int i = 0; i < KTOP; ++i) { s_fv[ql][i] = fv[i]; s_fi[ql][i] = fi[i]; }
        }
    }
    __syncthreads();

    // ---- outputs: scores (even warp) + gather split across the pair -------
    if (act) {
        if (half == 0 && lane < KTOP)
            out[(size_t)B * KTOP * DDIM + (size_t)qi * KTOP + lane] = s_fv[ql][lane];
        #pragma unroll
        for (int r = 0; r < KTOP / 2; ++r) {
            const int rr = half * (KTOP / 2) + r;
            const int n  = s_fi[ql][rr];
            if ((unsigned)n < (unsigned)N) {
                const float4* src = (const float4*)(mem + (size_t)n * DDIM);
                float4* dst = (float4*)(out + ((size_t)qi * KTOP + rr) * DDIM);
                dst[lane]      = src[lane];
                dst[lane + 32] = src[lane + 32];
            }
        }
    }
}

// ---------------- entry -----------------------------------------------------
extern "C" void kernel_launch(void* const* d_in, const int* in_sizes, int n_in,
                              void* d_out, int out_size) {
    const float* query = (const float*)d_in[0];
    const float* mem   = (const float*)d_in[1];
    float* out         = (float*)d_out;
    (void)n_in; (void)out_size;

    const int B = in_sizes[0] / DDIM;            // 2048
    const int N = in_sizes[1] / DDIM;            // 100000
    const int ntiles = (N + NT - 1) / NT;        // 782
    const int nrows_pad = ntiles * NT;           // 100096

    const int total_warps = nrows_pad + B;
    norm_kernel<<<(total_warps * 32 + 255) / 256, 256>>>(query, mem, B, N, nrows_pad);

    cudaFuncSetAttribute(gemm_topk_kernel,
                         cudaFuncAttributeMaxDynamicSharedMemorySize, SMEM_BYTES);
    dim3 grid(B / QT, NSPLIT);
    gemm_topk_kernel<<<grid, 256, SMEM_BYTES>>>(ntiles);

    rerank_kernel<<<(B + QPB - 1) / QPB, 256>>>(query, mem, out, B, N);
}